// round 3
// baseline (speedup 1.0000x reference)
#include <cuda_runtime.h>

#define LOG2E 1.4426950408889634f
#define N_EN  20000
#define M_MEN 256
#define TN 32   // entity lanes per block (threadIdx.x); each handles 2 entities
#define MG 8    // mention-groups per block (threadIdx.y)
#define RM 4    // mentions per thread

typedef unsigned long long ull;

__device__ __forceinline__ float ex2f(float x){float r;asm("ex2.approx.ftz.f32 %0,%1;":"=f"(r):"f"(x));return r;}
__device__ __forceinline__ float lg2f(float x){float r;asm("lg2.approx.ftz.f32 %0,%1;":"=f"(r):"f"(x));return r;}

__device__ __forceinline__ ull pk(float a,float b){ull r;asm("mov.b64 %0,{%1,%2};":"=l"(r):"f"(a),"f"(b));return r;}
__device__ __forceinline__ void upk(ull v,float&a,float&b){asm("mov.b64 {%0,%1},%2;":"=f"(a),"=f"(b):"l"(v));}
__device__ __forceinline__ ull ffma2(ull a,ull b,ull c){ull r;asm("fma.rn.f32x2 %0,%1,%2,%3;":"=l"(r):"l"(a),"l"(b),"l"(c));return r;}
__device__ __forceinline__ ull fmul2(ull a,ull b){ull r;asm("mul.rn.f32x2 %0,%1,%2;":"=l"(r):"l"(a),"l"(b));return r;}

// Degree-6 poly for ln(1+t), t in [0,1] (closed-form Chebyshev, z=3-2*sqrt2).
// G(t) > 0 on [0,1] so chunk products stay positive (no NaN from lg2).
struct PolyC { ull b6,b5,b4,b3,b2,b1,b0,ln2; };

// softplus (nats) for a pair; input y = x*log2e.
__device__ __forceinline__ ull sp_pair(float y0, float y1, const PolyC& C){
    float t0 = ex2f(-fabsf(y0));
    float t1 = ex2f(-fabsf(y1));
    float r0 = fmaxf(y0, 0.f);
    float r1 = fmaxf(y1, 0.f);
    ull tv = pk(t0,t1);
    ull rv = pk(r0,r1);
    ull p = ffma2(C.b6, tv, C.b5);
    p = ffma2(p, tv, C.b4);
    p = ffma2(p, tv, C.b3);
    p = ffma2(p, tv, C.b2);
    p = ffma2(p, tv, C.b1);
    p = ffma2(p, tv, C.b0);      // G(t)
    return ffma2(rv, C.ln2, p);  // relu*ln2 + G
}

// lg2( prod_{d=0..7} softplus(min(mZ,eZ)-max(mz,ez)) ) for one chunk.
__device__ __forceinline__ float chunk_lg2(const float* mz, const float* mZ,
                                           const float* ez, const float* eZ,
                                           const PolyC& C){
    ull prod = 0;
#pragma unroll
    for (int p = 0; p < 4; ++p){
        float y0 = fminf(mZ[2*p],   eZ[2*p])   - fmaxf(mz[2*p],   ez[2*p]);
        float y1 = fminf(mZ[2*p+1], eZ[2*p+1]) - fmaxf(mz[2*p+1], ez[2*p+1]);
        ull s = sp_pair(y0, y1, C);
        prod = p ? fmul2(prod, s) : s;
    }
    float pa, pb; upk(prod, pa, pb);
    return lg2f(pa * pb);
}

__device__ __forceinline__ void load8(const float* p, float* v){
    float4 a = *(const float4*)p;
    float4 b = *(const float4*)(p + 4);
    v[0]=a.x; v[1]=a.y; v[2]=a.z; v[3]=a.w;
    v[4]=b.x; v[5]=b.y; v[6]=b.z; v[7]=b.w;
}
__device__ __forceinline__ void load8s(const float* p, float* v){
    float4 a = *(const float4*)p;
    float4 b = *(const float4*)(p + 4);
    v[0]=a.x*LOG2E; v[1]=a.y*LOG2E; v[2]=a.z*LOG2E; v[3]=a.w*LOG2E;
    v[4]=b.x*LOG2E; v[5]=b.y*LOG2E; v[6]=b.z*LOG2E; v[7]=b.w*LOG2E;
}

__global__ __launch_bounds__(256, 2) void ivr_kernel(const float* __restrict__ men,
                                                     const float* __restrict__ en,
                                                     float* __restrict__ out){
    __shared__ float s_men[32][128];   // 32 mentions, prescaled by log2e
    __shared__ float s_gmp[256];
    __shared__ float s_gm[32];

    PolyC C;
    C.b6 = pk(-0.017415424f, -0.017415424f);
    C.b5 = pk( 0.08269552f,   0.08269552f);
    C.b4 = pk(-0.190359232f, -0.190359232f);
    C.b3 = pk( 0.31574968f,   0.31574968f);
    C.b2 = pk(-0.497373624f, -0.497373624f);
    C.b1 = pk( 0.9998477f,    0.9998477f);
    C.b0 = pk( 2.66e-6f,      2.66e-6f);
    C.ln2= pk( 0.69314718f,   0.69314718f);

    const int tid = threadIdx.y * TN + threadIdx.x;
    const int m0  = blockIdx.y * 32;

#pragma unroll
    for (int i = 0; i < 16; ++i){
        int idx = tid + i * 256;
        s_men[idx >> 7][idx & 127] = men[m0 * 128 + idx] * LOG2E;
    }
    __syncthreads();

    // per-mention self volume (same value path -> approximation error cancels)
    {
        int mi = tid >> 3, ci = tid & 7;
        float mzv[8], mZv[8];
        load8(&s_men[mi][ci*8], mzv);
        load8(&s_men[mi][64 + ci*8], mZv);
        s_gmp[tid] = chunk_lg2(mzv, mZv, mzv, mZv, C);
    }
    __syncthreads();
    if (tid < 32){
        float s = 0.f;
#pragma unroll
        for (int i = 0; i < 8; ++i) s += s_gmp[tid*8 + i];
        s_gm[tid] = s;
    }
    __syncthreads();

    const int n0 = blockIdx.x * 64 + threadIdx.x;        // entity 0
    const int n1 = n0 + 32;                              // entity 1
    const int c0 = n0 < N_EN ? n0 : (N_EN - 1);
    const int c1 = n1 < N_EN ? n1 : (N_EN - 1);
    const int mg = threadIdx.y;

    float acc0[RM], acc1[RM];
#pragma unroll
    for (int j = 0; j < RM; ++j){ acc0[j] = 0.f; acc1[j] = 0.f; }

    const float* e0 = en + (size_t)c0 * 128;
    const float* e1 = en + (size_t)c1 * 128;

#pragma unroll 1
    for (int c = 0; c < 8; ++c){
        float ez0[8], eZ0[8], ez1[8], eZ1[8];
        load8s(e0 + c*8,      ez0);
        load8s(e0 + 64 + c*8, eZ0);
        load8s(e1 + c*8,      ez1);
        load8s(e1 + 64 + c*8, eZ1);

#pragma unroll
        for (int j = 0; j < RM; ++j){
            float mzv[8], mZv[8];
            load8(&s_men[mg*RM + j][c*8],      mzv);
            load8(&s_men[mg*RM + j][64 + c*8], mZv);
            acc0[j] += chunk_lg2(mzv, mZv, ez0, eZ0, C);
            acc1[j] += chunk_lg2(mzv, mZv, ez1, eZ1, C);
        }
    }

#pragma unroll
    for (int j = 0; j < RM; ++j){
        int m = m0 + mg*RM + j;
        float g = s_gm[mg*RM + j];
        if (n0 < N_EN) out[(size_t)m * N_EN + n0] = ex2f(acc0[j] - g);
        if (n1 < N_EN) out[(size_t)m * N_EN + n1] = ex2f(acc1[j] - g);
    }
}

extern "C" void kernel_launch(void* const* d_in, const int* in_sizes, int n_in,
                              void* d_out, int out_size){
    const float* men = (const float*)d_in[0];
    const float* en  = (const float*)d_in[1];
    if (n_in >= 2 && in_sizes[0] > in_sizes[1]){
        const float* t = men; men = en; en = t;
    }
    float* out = (float*)d_out;

    dim3 block(TN, MG);
    dim3 grid((N_EN + 63) / 64, M_MEN / (MG * RM));
    ivr_kernel<<<grid, block>>>(men, en, out);
}

// round 5
// speedup vs baseline: 1.2605x; 1.2605x over previous
#include <cuda_runtime.h>

#define LOG2E 1.4426950408889634f
#define N_EN  20000
#define M_MEN 256
#define TN 64   // entities per block (threadIdx.x)
#define MG 4    // mention-groups per block (threadIdx.y)
#define RM 8    // mentions per thread

typedef unsigned long long ull;

// Packed (duplicated-lane) poly coefficients in constant memory -> LDCU/uniform
// path, keeps them out of the per-thread register budget.
// Degree-6 poly for ln(1+t), t in [0,1] (closed-form Chebyshev, z=3-2*sqrt2).
// G(t) > 0 on [0,1] so chunk products stay positive (no NaN from lg2).
__constant__ ull c_poly[8] = {
    0xBC8EAA8FBC8EAA8FULL, // b6 = -0.017415424
    0x3DA958BC3DA958BCULL, // b5 =  0.08269552
    0xBE42F3BFBE42F3BFULL, // b4 = -0.190359232
    0x3EA1A3F73EA1A3F7ULL, // b3 =  0.31574968
    0xBEFEA7ACBEFEA7ACULL, // b2 = -0.497373624
    0x3F7FF6043F7FF604ULL, // b1 =  0.9998477
    0x363282E3363282E3ULL, // b0 =  2.66e-6
    0x3F3172183F317218ULL, // ln2 = 0.69314718
};

__device__ __forceinline__ float ex2f(float x){float r;asm("ex2.approx.ftz.f32 %0,%1;":"=f"(r):"f"(x));return r;}
__device__ __forceinline__ float lg2f(float x){float r;asm("lg2.approx.ftz.f32 %0,%1;":"=f"(r):"f"(x));return r;}

__device__ __forceinline__ ull pk(float a,float b){ull r;asm("mov.b64 %0,{%1,%2};":"=l"(r):"f"(a),"f"(b));return r;}
__device__ __forceinline__ void upk(ull v,float&a,float&b){asm("mov.b64 {%0,%1},%2;":"=f"(a),"=f"(b):"l"(v));}
__device__ __forceinline__ ull ffma2(ull a,ull b,ull c){ull r;asm("fma.rn.f32x2 %0,%1,%2,%3;":"=l"(r):"l"(a),"l"(b),"l"(c));return r;}
__device__ __forceinline__ ull fmul2(ull a,ull b){ull r;asm("mul.rn.f32x2 %0,%1,%2;":"=l"(r):"l"(a),"l"(b));return r;}

// softplus (nats) for a pair; input y = x*log2e.
// s = relu(y)*ln2 + G(2^-|y|), G > 0 always => s > 0.
__device__ __forceinline__ ull sp_pair(float y0, float y1){
    float t0 = ex2f(-fabsf(y0));
    float t1 = ex2f(-fabsf(y1));
    float r0 = fmaxf(y0, 0.f);
    float r1 = fmaxf(y1, 0.f);
    ull tv = pk(t0,t1);
    ull rv = pk(r0,r1);
    ull p = ffma2(c_poly[0], tv, c_poly[1]);
    p = ffma2(p, tv, c_poly[2]);
    p = ffma2(p, tv, c_poly[3]);
    p = ffma2(p, tv, c_poly[4]);
    p = ffma2(p, tv, c_poly[5]);
    p = ffma2(p, tv, c_poly[6]);      // G(t)
    return ffma2(rv, c_poly[7], p);   // relu*ln2 + G
}

// lg2( prod_{d in chunk of 8} softplus(min(mZ,eZ)-max(mz,ez)) )
__device__ __forceinline__ float chunk_lg2(const float* mz, const float* mZ,
                                           const float* ez, const float* eZ){
    ull prod = 0;
#pragma unroll
    for (int p = 0; p < 4; ++p){
        float y0 = fminf(mZ[2*p],   eZ[2*p])   - fmaxf(mz[2*p],   ez[2*p]);
        float y1 = fminf(mZ[2*p+1], eZ[2*p+1]) - fmaxf(mz[2*p+1], ez[2*p+1]);
        ull s = sp_pair(y0, y1);
        prod = p ? fmul2(prod, s) : s;
    }
    float pa, pb; upk(prod, pa, pb);
    return lg2f(pa * pb);
}

__device__ __forceinline__ void load8(const float* p, float* v){
    float4 a = *(const float4*)p;
    float4 b = *(const float4*)(p + 4);
    v[0]=a.x; v[1]=a.y; v[2]=a.z; v[3]=a.w;
    v[4]=b.x; v[5]=b.y; v[6]=b.z; v[7]=b.w;
}
__device__ __forceinline__ void load8s(const float* p, float* v){
    float4 a = *(const float4*)p;
    float4 b = *(const float4*)(p + 4);
    v[0]=a.x*LOG2E; v[1]=a.y*LOG2E; v[2]=a.z*LOG2E; v[3]=a.w*LOG2E;
    v[4]=b.x*LOG2E; v[5]=b.y*LOG2E; v[6]=b.z*LOG2E; v[7]=b.w*LOG2E;
}

__global__ __launch_bounds__(256, 4) void ivr_kernel(const float* __restrict__ men,
                                                     const float* __restrict__ en,
                                                     float* __restrict__ out){
    __shared__ float s_men[32][128];   // 32 mentions, prescaled by log2e
    __shared__ float s_gmp[256];
    __shared__ float s_gm[32];

    const int tid = threadIdx.y * TN + threadIdx.x;
    const int m0  = blockIdx.y * 32;

#pragma unroll
    for (int i = 0; i < 16; ++i){
        int idx = tid + i * 256;
        s_men[idx >> 7][idx & 127] = men[m0 * 128 + idx] * LOG2E;
    }
    __syncthreads();

    // per-mention self volume (identical value path -> approx error cancels)
    {
        int mi = tid >> 3, ci = tid & 7;
        float mzv[8], mZv[8];
        load8(&s_men[mi][ci*8],      mzv);
        load8(&s_men[mi][64 + ci*8], mZv);
        s_gmp[tid] = chunk_lg2(mzv, mZv, mzv, mZv);
    }
    __syncthreads();
    if (tid < 32){
        float s = 0.f;
#pragma unroll
        for (int i = 0; i < 8; ++i) s += s_gmp[tid*8 + i];
        s_gm[tid] = s;
    }
    __syncthreads();

    const int n = blockIdx.x * TN + threadIdx.x;
    if (n >= N_EN) return;

    const int mg = threadIdx.y;
    float acc[RM];
#pragma unroll
    for (int j = 0; j < RM; ++j) acc[j] = 0.f;

    const float* erow = en + (size_t)n * 128;

#pragma unroll 1
    for (int c = 0; c < 8; ++c){
        float ez[8], eZ[8];
        load8s(erow + c*8,      ez);
        load8s(erow + 64 + c*8, eZ);

#pragma unroll
        for (int j = 0; j < RM; ++j){
            float mzv[8], mZv[8];
            load8(&s_men[mg*RM + j][c*8],      mzv);   // smem broadcast
            load8(&s_men[mg*RM + j][64 + c*8], mZv);
            acc[j] += chunk_lg2(mzv, mZv, ez, eZ);
        }
    }

#pragma unroll
    for (int j = 0; j < RM; ++j){
        int m = m0 + mg*RM + j;
        out[(size_t)m * N_EN + n] = ex2f(acc[j] - s_gm[mg*RM + j]);
    }
}

extern "C" void kernel_launch(void* const* d_in, const int* in_sizes, int n_in,
                              void* d_out, int out_size){
    const float* men = (const float*)d_in[0];
    const float* en  = (const float*)d_in[1];
    if (n_in >= 2 && in_sizes[0] > in_sizes[1]){
        const float* t = men; men = en; en = t;
    }
    float* out = (float*)d_out;

    dim3 block(TN, MG);
    dim3 grid((N_EN + TN - 1) / TN, M_MEN / (MG * RM));
    ivr_kernel<<<grid, block>>>(men, en, out);
}